// round 12
// baseline (speedup 1.0000x reference)
#include <cuda_runtime.h>
#include <math.h>

#define NT        768
#define NACT      720          // 240 transitions x 3 subs
#define SUBQ      8            // frames per sub-thread per block
#define NFRAMES   6000
#define NTEMPI    60
#define NBEATS    4
#define NTRANS    240
#define LT_STRIDE 61
#define LT2SZ     (NBEATS * NTEMPI * LT_STRIDE)   // 14640
#define SPAD      15360
#define BFR       24           // frames per block; needs BFR <= minL-1 (minL=28)
#define WREG      44           // fixed register window width (R6-proven)

// -------- smem layout (floats) --------
#define OFF_VV    0
#define OFF_LT2   (OFF_VV + SPAD)                 // 15360
#define OFF_SC    (OFF_LT2 + LT2SZ)               // 30000
#define OFF_CC    (OFF_SC + BFR * 256)            // 36144
#define OFF_PREV  (OFF_CC + 64)
#define OFF_BASE  (OFF_PREV + NTRANS)
#define OFF_LO    (OFF_BASE + NTRANS)
#define OFF_HI    (OFF_LO + NTRANS)
#define OFF_RV    (OFF_HI + NTRANS)
#define OFF_RI    (OFF_RV + NT)
#define OFF_SUM   (OFF_RI + NT)
#define OFF_IVL   (OFF_SUM + 8)
#define SMEM_FLOATS (OFF_IVL + SPAD / 2)
#define SMEM_BYTES  (SMEM_FLOATS * 4)

__device__ float4 g_c4[NFRAMES];                  // {d1-d0, d2-d0, d0, 0}
__device__ float  g_cand[NFRAMES * NTRANS];       // gathered candidates (backtrace)

__global__ void dens_kernel(const float* __restrict__ acts) {
    int t = blockIdx.x * blockDim.x + threadIdx.x;
    if (t < NFRAMES) {
        float ab = acts[2 * t];
        float ad = acts[2 * t + 1];
        float d0 = logf((1.0f - ab - ad) / 15.0f);
        float d1 = logf(ab);
        float d2 = logf(ad);
        g_c4[t] = make_float4(d1 - d0, d2 - d0, d0, 0.0f);
    }
}

__global__ __launch_bounds__(NT, 1)
void viterbi_kernel(const float* __restrict__ log_trans,
                    const int*   __restrict__ prev_last,
                    const int*   __restrict__ first_states,
                    const int*   __restrict__ pointer,
                    float*       __restrict__ out,
                    int S, int out_size)
{
    extern __shared__ float sm[];
    float*          vv    = sm + OFF_VV;
    float*          lt2   = sm + OFF_LT2;
    float*          sC    = sm + OFF_SC;
    float*          sCC   = sm + OFF_CC;
    int*            sPrev = (int*)(sm + OFF_PREV);
    int*            sBase = (int*)(sm + OFF_BASE);
    int*            sLo   = (int*)(sm + OFF_LO);
    int*            sHi   = (int*)(sm + OFF_HI);
    float*          rv    = sm + OFF_RV;
    int*            ri    = (int*)(sm + OFF_RI);
    float*          sSum  = sm + OFF_SUM;
    unsigned short* sIvl  = (unsigned short*)(sm + OFF_IVL);

    const int  tid   = threadIdx.x;
    const int  nsb   = S / NBEATS;
    const bool act   = (tid < NACT);
    const int  p     = act ? (tid % NTRANS) : 0;
    const int  qBase = act ? ((tid / NTRANS) * SUBQ) : 0;   // 0, 8, 16

    // ================= init =================
    float v0 = -logf((float)S);
    for (int s = tid; s < SPAD; s += NT) vv[s] = v0;
    for (int idx = tid; idx < NBEATS * NTEMPI * NTEMPI; idx += NT) {
        int b = idx / (NTEMPI * NTEMPI);
        int r = (idx - b * NTEMPI * NTEMPI) / NTEMPI;
        int c = idx % NTEMPI;
        lt2[b * NTEMPI * LT_STRIDE + r * LT_STRIDE + c] = log_trans[idx];
    }
    if (tid < NTRANS) {
        sPrev[tid] = prev_last[tid];
        sBase[tid] = first_states[tid];
    }
    // total d0 (for logp) — 768->256 fold then power-of-2 tree
    {
        float acc = 0.0f;
        for (int t = tid; t < NFRAMES; t += NT) acc += g_c4[t].z;
        rv[tid] = acc;
        __syncthreads();
        if (tid < 256) rv[tid] += rv[tid + 256] + rv[tid + 512];
        __syncthreads();
        for (int off = 128; off > 0; off >>= 1) {
            if (tid < off) rv[tid] += rv[tid + off];
            __syncthreads();
        }
        if (tid == 0) *sSum = rv[0];
        __syncthreads();
    }

    // per-transition statics (per sub-thread)
    int b60 = 0, i60 = 0, myBase = 0, myL = 1, srcBase = 0, myM = 0, psel = 0, Lo = 0;
    float rr[WREG];
    if (act) {
        b60 = p / NTEMPI;
        i60 = p - b60 * NTEMPI;
        myBase = sBase[p];
        int end = (i60 < NTEMPI - 1) ? sBase[p + 1] : (b60 + 1) * nsb;
        myL = end - myBase;
        srcBase = (b60 == 0) ? (myBase + 3 * nsb) : (myBase - nsb);
        for (int o = 1; o < myL && o <= 7; o++) {
            if (pointer[myBase + o] != 0) myM = o; else break;
        }
        psel = (pointer[myBase] == 2) ? 1 : 0;
        const float* row = lt2 + b60 * NTEMPI * LT_STRIDE + i60 * LT_STRIDE;
        int lo = NTEMPI, hi = -1;
        for (int j = 0; j < NTEMPI; j++)
            if (row[j] > -1e29f) { if (j < lo) lo = j; hi = j; }
        Lo = lo; if (Lo > NTEMPI - WREG) Lo = NTEMPI - WREG; if (Lo < 0) Lo = 0;
        #pragma unroll
        for (int jj = 0; jj < WREG; jj++) rr[jj] = row[Lo + jj];
        if (tid < NTRANS) {     // one-time setup by sub 0
            sLo[p] = lo; sHi[p] = hi;
            for (int o = 0; o < myL; o++) sIvl[myBase + o] = (unsigned short)p;
            // initial-value fix corrections (folded future fixes)
            const float* c4f = (const float*)g_c4;
            float run = 0.0f;
            for (int i = 0; i < myM; i++) {
                run += c4f[4 * i + psel];
                vv[myBase + (myM - 1 - i)] = v0 + run;
            }
        }
    }
    __syncthreads();

    int k = myL - 1;    // rotating slot offset of state o=0 (at block start)

    // ================= 250 blocks x 24 frames =================
    for (int t0 = 0; t0 < NFRAMES; t0 += BFR) {
        // ---- gather phase: snapshot candidates for this thread's 8 frames ----
        if (act) {
            #pragma unroll
            for (int e = 0; e < SUBQ; e++) {
                int q  = qBase + e;
                int kg = k - q; if (kg < 0) kg += myL;
                float val = vv[srcBase + kg];
                sC[q * 256 + p] = val;
                g_cand[(t0 + q) * NTRANS + p] = val;
            }
        }
        if (tid >= NACT && tid < NACT + BFR + 8) {
            int u = tid - NACT;
            int fr = t0 + u; if (fr > NFRAMES - 1) fr = NFRAMES - 1;
            float4 c = g_c4[fr];
            sCC[2 * u]     = c.x;
            sCC[2 * u + 1] = c.y;
        }
        __syncthreads();

        // ---- compute phase: 8 independent frames per thread ----
        if (act) {
            const float* ccp = sCC + psel;
            #pragma unroll 1
            for (int e = 0; e < SUBQ; e++) {
                int q  = qBase + e;
                int kw = k - q; if (kw < 0) kw += myL;
                const float* c = sC + q * 256 + b60 * NTEMPI + Lo;
                float m0 = -3.0e38f, m1 = -3.0e38f, m2 = -3.0e38f, m3 = -3.0e38f;
                #pragma unroll
                for (int jj = 0; jj < WREG; jj += 4) {
                    m0 = fmaxf(m0, c[jj]     + rr[jj]);
                    m1 = fmaxf(m1, c[jj + 1] + rr[jj + 1]);
                    m2 = fmaxf(m2, c[jj + 2] + rr[jj + 2]);
                    m3 = fmaxf(m3, c[jj + 3] + rr[jj + 3]);
                }
                float val = fmaxf(fmaxf(m0, m1), fmaxf(m2, m3));
                val += ccp[2 * q];
                #pragma unroll 1
                for (int i = 1; i <= myM; i++) {
                    if (t0 + q + i <= NFRAMES - 1) val += ccp[2 * (q + i)];
                }
                vv[myBase + kw] = val;
            }
            k -= BFR; if (k < 0) k += myL;
        }
        __syncthreads();
    }

    // ================= argmax over final v (first-index tie-break) ============
    float bv = -3.0e38f;
    int   bi = 0x7FFFFFFF;
    if (tid < NTRANS) {
        int r = NFRAMES % myL;
        for (int o = 0; o < myL; o++) {
            int so = o - r; if (so < 0) so += myL;
            float x = vv[myBase + so];
            if (x > bv) { bv = x; bi = myBase + o; }
        }
    }
    rv[tid] = bv; ri[tid] = bi;
    __syncthreads();
    // 768 -> 256 fold (lexicographic merge is order-independent)
    if (tid < 256) {
        #pragma unroll
        for (int g = 1; g < 3; g++) {
            float xv = rv[tid + 256 * g]; int xi = ri[tid + 256 * g];
            if (xv > rv[tid] || (xv == rv[tid] && xi < ri[tid])) { rv[tid] = xv; ri[tid] = xi; }
        }
    }
    __syncthreads();
    for (int off = 128; off > 0; off >>= 1) {
        if (tid < off) {
            float xv = rv[tid + off]; int xi = ri[tid + off];
            if (xv > rv[tid] || (xv == rv[tid] && xi < ri[tid])) { rv[tid] = xv; ri[tid] = xi; }
        }
        __syncthreads();
    }

    // ================= backtrace (thread 0) =================
    if (tid == 0) {
        int s = ri[0];
        if (out_size > NFRAMES) out[NFRAMES] = rv[0] + *sSum;
        out[NFRAMES - 1] = (float)s;
        int t = NFRAMES - 1;
        while (t >= 1) {
            int iv = sIvl[s];
            int o  = s - sBase[iv];
            int steps = (o < t) ? o : t;
            for (int j = 1; j <= steps; j++) out[t - j] = (float)(s - j);
            t -= steps; s -= steps;
            if (t >= 1) {
                int b = iv / NTEMPI, i = iv - b * NTEMPI;
                const float* row  = lt2 + b * NTEMPI * LT_STRIDE + i * LT_STRIDE;
                const float* cand = g_cand + t * NTRANS + b * NTEMPI;
                int lo = sLo[iv], hi = sHi[iv];
                float best = -3.0e38f; int arg = lo;
                for (int j = lo; j <= hi; j++) {
                    float sc = cand[j] + row[j];
                    if (sc > best) { best = sc; arg = j; }
                }
                int pp = sPrev[b * NTEMPI + arg];
                out[t - 1] = (float)pp;
                s = pp; t--;
            }
        }
    }
}

extern "C" void kernel_launch(void* const* d_in, const int* in_sizes, int n_in,
                              void* d_out, int out_size) {
    const float* acts         = (const float*)d_in[0];
    const float* log_trans    = (const float*)d_in[1];
    const int*   prev_last    = (const int*)d_in[2];
    const int*   first_states = (const int*)d_in[3];
    const int*   pointer      = (const int*)d_in[4];
    int S = in_sizes[4];

    cudaFuncSetAttribute(viterbi_kernel, cudaFuncAttributeMaxDynamicSharedMemorySize, SMEM_BYTES);

    dens_kernel<<<(NFRAMES + 255) / 256, 256>>>(acts);
    viterbi_kernel<<<1, NT, SMEM_BYTES>>>(log_trans, prev_last, first_states, pointer,
                                          (float*)d_out, S, out_size);
}

// round 13
// speedup vs baseline: 1.1186x; 1.1186x over previous
#include <cuda_runtime.h>
#include <math.h>

#define NT        768
#define NACT      720          // 240 transitions x 3 subs
#define SUBQ      8            // frames per sub-thread per block
#define NFRAMES   6000
#define NTEMPI    60
#define NBEATS    4
#define NTRANS    240
#define LT_STRIDE 61
#define LT2SZ     (NBEATS * NTEMPI * LT_STRIDE)   // 14640
#define SPAD      15360
#define BFR       24           // frames per block; needs BFR <= minL-1 (minL=28)
#define WREG      48           // packed window width (12 x LDS.128)

// -------- smem layout (floats) — identical to R12 --------
#define OFF_VV    0
#define OFF_LT2   (OFF_VV + SPAD)                 // 15360
#define OFF_SC    (OFF_LT2 + LT2SZ)               // 30000 (16B aligned)
#define OFF_CC    (OFF_SC + BFR * 256)            // 36144
#define OFF_PREV  (OFF_CC + 64)
#define OFF_BASE  (OFF_PREV + NTRANS)
#define OFF_LO    (OFF_BASE + NTRANS)
#define OFF_HI    (OFF_LO + NTRANS)
#define OFF_RV    (OFF_HI + NTRANS)
#define OFF_RI    (OFF_RV + NT)
#define OFF_SUM   (OFF_RI + NT)
#define OFF_IVL   (OFF_SUM + 8)
#define SMEM_FLOATS (OFF_IVL + SPAD / 2)
#define SMEM_BYTES  (SMEM_FLOATS * 4)

#define ADDX2(out, a, b) asm("add.rn.f32x2 %0, %1, %2;" : "=l"(out) : "l"(a), "l"(b))
#define UNPK(lo, hi, in) asm("mov.b64 {%0, %1}, %2;" : "=f"(lo), "=f"(hi) : "l"(in))
#define PK(out, lo, hi)  asm("mov.b64 %0, {%1, %2};" : "=l"(out) : "f"(lo), "f"(hi))

__device__ float4 g_c4[NFRAMES];                  // {d1-d0, d2-d0, d0, 0}
__device__ float  g_cand[NFRAMES * NTRANS];       // gathered candidates (backtrace)

__global__ void dens_kernel(const float* __restrict__ acts) {
    int t = blockIdx.x * blockDim.x + threadIdx.x;
    if (t < NFRAMES) {
        float ab = acts[2 * t];
        float ad = acts[2 * t + 1];
        float d0 = logf((1.0f - ab - ad) / 15.0f);
        float d1 = logf(ab);
        float d2 = logf(ad);
        g_c4[t] = make_float4(d1 - d0, d2 - d0, d0, 0.0f);
    }
}

__global__ __launch_bounds__(NT, 1)
void viterbi_kernel(const float* __restrict__ log_trans,
                    const int*   __restrict__ prev_last,
                    const int*   __restrict__ first_states,
                    const int*   __restrict__ pointer,
                    float*       __restrict__ out,
                    int S, int out_size)
{
    extern __shared__ float sm[];
    float*          vv    = sm + OFF_VV;
    float*          lt2   = sm + OFF_LT2;
    float*          sC    = sm + OFF_SC;
    float*          sCC   = sm + OFF_CC;
    int*            sPrev = (int*)(sm + OFF_PREV);
    int*            sBase = (int*)(sm + OFF_BASE);
    int*            sLo   = (int*)(sm + OFF_LO);
    int*            sHi   = (int*)(sm + OFF_HI);
    float*          rv    = sm + OFF_RV;
    int*            ri    = (int*)(sm + OFF_RI);
    float*          sSum  = sm + OFF_SUM;
    unsigned short* sIvl  = (unsigned short*)(sm + OFF_IVL);

    const int  tid   = threadIdx.x;
    const int  nsb   = S / NBEATS;
    const bool act   = (tid < NACT);
    const int  p     = act ? (tid % NTRANS) : 0;
    const int  qBase = act ? ((tid / NTRANS) * SUBQ) : 0;   // 0, 8, 16

    // ================= init =================
    float v0 = -logf((float)S);
    for (int s = tid; s < SPAD; s += NT) vv[s] = v0;
    for (int idx = tid; idx < NBEATS * NTEMPI * NTEMPI; idx += NT) {
        int b = idx / (NTEMPI * NTEMPI);
        int r = (idx - b * NTEMPI * NTEMPI) / NTEMPI;
        int c = idx % NTEMPI;
        lt2[b * NTEMPI * LT_STRIDE + r * LT_STRIDE + c] = log_trans[idx];
    }
    if (tid < NTRANS) {
        sPrev[tid] = prev_last[tid];
        sBase[tid] = first_states[tid];
    }
    // total d0 (for logp) — 768->256 fold then power-of-2 tree
    {
        float acc = 0.0f;
        for (int t = tid; t < NFRAMES; t += NT) acc += g_c4[t].z;
        rv[tid] = acc;
        __syncthreads();
        if (tid < 256) rv[tid] += rv[tid + 256] + rv[tid + 512];
        __syncthreads();
        for (int off = 128; off > 0; off >>= 1) {
            if (tid < off) rv[tid] += rv[tid + off];
            __syncthreads();
        }
        if (tid == 0) *sSum = rv[0];
        __syncthreads();
    }

    // per-transition statics (per sub-thread)
    int b60 = 0, i60 = 0, myBase = 0, myL = 1, srcBase = 0, myM = 0, psel = 0, cOff = 0;
    unsigned long long rP[WREG / 2];
    if (act) {
        b60 = p / NTEMPI;
        i60 = p - b60 * NTEMPI;
        myBase = sBase[p];
        int end = (i60 < NTEMPI - 1) ? sBase[p + 1] : (b60 + 1) * nsb;
        myL = end - myBase;
        srcBase = (b60 == 0) ? (myBase + 3 * nsb) : (myBase - nsb);
        for (int o = 1; o < myL && o <= 7; o++) {
            if (pointer[myBase + o] != 0) myM = o; else break;
        }
        psel = (pointer[myBase] == 2) ? 1 : 0;
        const float* row = lt2 + b60 * NTEMPI * LT_STRIDE + i60 * LT_STRIDE;
        int lo = NTEMPI, hi = -1;
        for (int j = 0; j < NTEMPI; j++)
            if (row[j] > -1e29f) { if (j < lo) lo = j; hi = j; }
        int Lo4 = lo & ~3;
        if (Lo4 > NTEMPI - WREG) Lo4 = NTEMPI - WREG;   // clamp to 12: window [12,60)
        cOff = b60 * NTEMPI + Lo4;                      // divisible by 4 -> 16B aligned
        #pragma unroll
        for (int m = 0; m < WREG / 2; m++) {
            PK(rP[m], row[Lo4 + 2 * m], row[Lo4 + 2 * m + 1]);
        }
        if (tid < NTRANS) {     // one-time setup by sub 0
            sLo[p] = lo; sHi[p] = hi;
            for (int o = 0; o < myL; o++) sIvl[myBase + o] = (unsigned short)p;
            // initial-value fix corrections (folded future fixes)
            const float* c4f = (const float*)g_c4;
            float run = 0.0f;
            for (int i = 0; i < myM; i++) {
                run += c4f[4 * i + psel];
                vv[myBase + (myM - 1 - i)] = v0 + run;
            }
        }
    }
    __syncthreads();

    int k = myL - 1;    // rotating slot offset of state o=0 (at block start)

    // ================= 250 blocks x 24 frames =================
    for (int t0 = 0; t0 < NFRAMES; t0 += BFR) {
        // ---- gather phase: snapshot candidates for this thread's 8 frames ----
        if (act) {
            #pragma unroll
            for (int e = 0; e < SUBQ; e++) {
                int q  = qBase + e;
                int kg = k - q; if (kg < 0) kg += myL;
                float val = vv[srcBase + kg];
                sC[q * 256 + p] = val;
                g_cand[(t0 + q) * NTRANS + p] = val;
            }
        }
        if (tid >= NACT && tid < NACT + BFR + 8) {
            int u = tid - NACT;
            int fr = t0 + u; if (fr > NFRAMES - 1) fr = NFRAMES - 1;
            float4 c = g_c4[fr];
            sCC[2 * u]     = c.x;
            sCC[2 * u + 1] = c.y;
        }
        __syncthreads();

        // ---- compute phase: 8 independent frames per thread ----
        if (act) {
            const float* ccp = sCC + psel;
            #pragma unroll 1
            for (int e = 0; e < SUBQ; e++) {
                int q  = qBase + e;
                int kw = k - q; if (kw < 0) kw += myL;
                const ulonglong2* c16 = (const ulonglong2*)(sC + q * 256 + cOff);
                float m0 = -3.0e38f, m1 = -3.0e38f, m2 = -3.0e38f, m3 = -3.0e38f;
                #pragma unroll
                for (int g = 0; g < WREG / 4; g++) {
                    ulonglong2 A = c16[g];
                    unsigned long long s0, s1;
                    float x, y;
                    ADDX2(s0, A.x, rP[2 * g]);     UNPK(x, y, s0);
                    m0 = fmaxf(m0, x); m1 = fmaxf(m1, y);
                    ADDX2(s1, A.y, rP[2 * g + 1]); UNPK(x, y, s1);
                    m2 = fmaxf(m2, x); m3 = fmaxf(m3, y);
                }
                float val = fmaxf(fmaxf(m0, m1), fmaxf(m2, m3));
                val += ccp[2 * q];
                #pragma unroll 1
                for (int i = 1; i <= myM; i++) {
                    if (t0 + q + i <= NFRAMES - 1) val += ccp[2 * (q + i)];
                }
                vv[myBase + kw] = val;
            }
            k -= BFR; if (k < 0) k += myL;
        }
        __syncthreads();
    }

    // ================= argmax over final v (first-index tie-break) ============
    float bv = -3.0e38f;
    int   bi = 0x7FFFFFFF;
    if (tid < NTRANS) {
        int r = NFRAMES % myL;
        for (int o = 0; o < myL; o++) {
            int so = o - r; if (so < 0) so += myL;
            float x = vv[myBase + so];
            if (x > bv) { bv = x; bi = myBase + o; }
        }
    }
    rv[tid] = bv; ri[tid] = bi;
    __syncthreads();
    // 768 -> 256 fold (lexicographic merge is order-independent)
    if (tid < 256) {
        #pragma unroll
        for (int g = 1; g < 3; g++) {
            float xv = rv[tid + 256 * g]; int xi = ri[tid + 256 * g];
            if (xv > rv[tid] || (xv == rv[tid] && xi < ri[tid])) { rv[tid] = xv; ri[tid] = xi; }
        }
    }
    __syncthreads();
    for (int off = 128; off > 0; off >>= 1) {
        if (tid < off) {
            float xv = rv[tid + off]; int xi = ri[tid + off];
            if (xv > rv[tid] || (xv == rv[tid] && xi < ri[tid])) { rv[tid] = xv; ri[tid] = xi; }
        }
        __syncthreads();
    }

    // ================= backtrace (thread 0) =================
    if (tid == 0) {
        int s = ri[0];
        if (out_size > NFRAMES) out[NFRAMES] = rv[0] + *sSum;
        out[NFRAMES - 1] = (float)s;
        int t = NFRAMES - 1;
        while (t >= 1) {
            int iv = sIvl[s];
            int o  = s - sBase[iv];
            int steps = (o < t) ? o : t;
            for (int j = 1; j <= steps; j++) out[t - j] = (float)(s - j);
            t -= steps; s -= steps;
            if (t >= 1) {
                int b = iv / NTEMPI, i = iv - b * NTEMPI;
                const float* row  = lt2 + b * NTEMPI * LT_STRIDE + i * LT_STRIDE;
                const float* cand = g_cand + t * NTRANS + b * NTEMPI;
                int lo = sLo[iv], hi = sHi[iv];
                float best = -3.0e38f; int arg = lo;
                for (int j = lo; j <= hi; j++) {
                    float sc = cand[j] + row[j];
                    if (sc > best) { best = sc; arg = j; }
                }
                int pp = sPrev[b * NTEMPI + arg];
                out[t - 1] = (float)pp;
                s = pp; t--;
            }
        }
    }
}

extern "C" void kernel_launch(void* const* d_in, const int* in_sizes, int n_in,
                              void* d_out, int out_size) {
    const float* acts         = (const float*)d_in[0];
    const float* log_trans    = (const float*)d_in[1];
    const int*   prev_last    = (const int*)d_in[2];
    const int*   first_states = (const int*)d_in[3];
    const int*   pointer      = (const int*)d_in[4];
    int S = in_sizes[4];

    cudaFuncSetAttribute(viterbi_kernel, cudaFuncAttributeMaxDynamicSharedMemorySize, SMEM_BYTES);

    dens_kernel<<<(NFRAMES + 255) / 256, 256>>>(acts);
    viterbi_kernel<<<1, NT, SMEM_BYTES>>>(log_trans, prev_last, first_states, pointer,
                                          (float*)d_out, S, out_size);
}

// round 16
// speedup vs baseline: 1.2521x; 1.1193x over previous
#include <cuda_runtime.h>
#include <math.h>

#define NT        768
#define NACT      720          // 240 transitions x 3 subs
#define SUBQ      8            // frames per sub-thread per block
#define NFRAMES   6000
#define NTEMPI    60
#define NBEATS    4
#define NTRANS    240
#define LT_STRIDE 61
#define LT2SZ     (NBEATS * NTEMPI * LT_STRIDE)   // 14640
#define SPAD      15360
#define BFR       24           // frames per block; needs BFR <= minL-1 (minL=28)
#define WREG      40           // packed window width (10 x LDS.128)

// -------- smem layout (floats) --------
#define OFF_VV    0
#define OFF_LT2   (OFF_VV + SPAD)                 // 15360
#define OFF_SC    (OFF_LT2 + LT2SZ)               // 30000 (16B aligned)
#define OFF_CC    (OFF_SC + BFR * 256)            // 36144
#define OFF_FOLD  (OFF_CC + 64)                   // 384 fold-sum entries
#define OFF_PREV  (OFF_FOLD + 384)
#define OFF_BASE  (OFF_PREV + NTRANS)
#define OFF_LO    (OFF_BASE + NTRANS)
#define OFF_HI    (OFF_LO + NTRANS)
#define OFF_RV    (OFF_HI + NTRANS)
#define OFF_RI    (OFF_RV + NT)
#define OFF_SUM   (OFF_RI + NT)
#define OFF_IVL   (OFF_SUM + 8)
#define SMEM_FLOATS (OFF_IVL + SPAD / 2)
#define SMEM_BYTES  (SMEM_FLOATS * 4)

#define ADDX2(out, a, b) asm("add.rn.f32x2 %0, %1, %2;" : "=l"(out) : "l"(a), "l"(b))
#define UNPK(lo, hi, in) asm("mov.b64 {%0, %1}, %2;" : "=f"(lo), "=f"(hi) : "l"(in))
#define PK(out, lo, hi)  asm("mov.b64 %0, {%1, %2};" : "=l"(out) : "f"(lo), "f"(hi))

__device__ float4 g_c4[NFRAMES];                  // {d1-d0, d2-d0, d0, 0}
__device__ float  g_cand[NFRAMES * NTRANS];       // gathered candidates (backtrace)

__global__ void dens_kernel(const float* __restrict__ acts) {
    int t = blockIdx.x * blockDim.x + threadIdx.x;
    if (t < NFRAMES) {
        float ab = acts[2 * t];
        float ad = acts[2 * t + 1];
        float d0 = logf((1.0f - ab - ad) / 15.0f);
        float d1 = logf(ab);
        float d2 = logf(ad);
        g_c4[t] = make_float4(d1 - d0, d2 - d0, d0, 0.0f);
    }
}

__global__ __launch_bounds__(NT, 1)
void viterbi_kernel(const float* __restrict__ log_trans,
                    const int*   __restrict__ prev_last,
                    const int*   __restrict__ first_states,
                    const int*   __restrict__ pointer,
                    float*       __restrict__ out,
                    int S, int out_size)
{
    extern __shared__ float sm[];
    float*          vv    = sm + OFF_VV;
    float*          lt2   = sm + OFF_LT2;
    float*          sC    = sm + OFF_SC;
    float*          sCC   = sm + OFF_CC;
    float*          foldT = sm + OFF_FOLD;
    int*            sPrev = (int*)(sm + OFF_PREV);
    int*            sBase = (int*)(sm + OFF_BASE);
    int*            sLo   = (int*)(sm + OFF_LO);
    int*            sHi   = (int*)(sm + OFF_HI);
    float*          rv    = sm + OFF_RV;
    int*            ri    = (int*)(sm + OFF_RI);
    float*          sSum  = sm + OFF_SUM;
    unsigned short* sIvl  = (unsigned short*)(sm + OFF_IVL);

    const int  tid   = threadIdx.x;
    const int  nsb   = S / NBEATS;
    const bool act   = (tid < NACT);
    const int  p     = act ? (tid % NTRANS) : 0;
    const int  qBase = act ? ((tid / NTRANS) * SUBQ) : 0;   // 0, 8, 16

    // ================= init =================
    float v0 = -logf((float)S);
    for (int s = tid; s < SPAD; s += NT) vv[s] = v0;
    for (int idx = tid; idx < NBEATS * NTEMPI * NTEMPI; idx += NT) {
        int b = idx / (NTEMPI * NTEMPI);
        int r = (idx - b * NTEMPI * NTEMPI) / NTEMPI;
        int c = idx % NTEMPI;
        lt2[b * NTEMPI * LT_STRIDE + r * LT_STRIDE + c] = log_trans[idx];
    }
    if (tid < NTRANS) {
        sPrev[tid] = prev_last[tid];
        sBase[tid] = first_states[tid];
    }
    // total d0 (for logp) — 768->256 fold then power-of-2 tree
    {
        float acc = 0.0f;
        for (int t = tid; t < NFRAMES; t += NT) acc += g_c4[t].z;
        rv[tid] = acc;
        __syncthreads();
        if (tid < 256) rv[tid] += rv[tid + 256] + rv[tid + 512];
        __syncthreads();
        for (int off = 128; off > 0; off >>= 1) {
            if (tid < off) rv[tid] += rv[tid + off];
            __syncthreads();
        }
        if (tid == 0) *sSum = rv[0];
        __syncthreads();
    }

    // per-transition statics (per sub-thread)
    int b60 = 0, i60 = 0, myBase = 0, myL = 1, srcBase = 0, myM = 0, psel = 0, cOff = 0;
    unsigned long long rP[WREG / 2];
    if (act) {
        b60 = p / NTEMPI;
        i60 = p - b60 * NTEMPI;
        myBase = sBase[p];
        int end = (i60 < NTEMPI - 1) ? sBase[p + 1] : (b60 + 1) * nsb;
        myL = end - myBase;
        srcBase = (b60 == 0) ? (myBase + 3 * nsb) : (myBase - nsb);
        for (int o = 1; o < myL && o <= 7; o++) {
            if (pointer[myBase + o] != 0) myM = o; else break;
        }
        psel = (pointer[myBase] == 2) ? 1 : 0;
        const float* row = lt2 + b60 * NTEMPI * LT_STRIDE + i60 * LT_STRIDE;
        int lo = NTEMPI, hi = -1;
        for (int j = 0; j < NTEMPI; j++)
            if (row[j] > -1e29f) { if (j < lo) lo = j; hi = j; }
        int Lo4 = lo & ~3;
        if (Lo4 > NTEMPI - WREG) Lo4 = NTEMPI - WREG;   // clamp to 20: window [20,60)
        cOff = b60 * NTEMPI + Lo4;                      // divisible by 4 -> 16B aligned
        #pragma unroll
        for (int m = 0; m < WREG / 2; m++) {
            PK(rP[m], row[Lo4 + 2 * m], row[Lo4 + 2 * m + 1]);
        }
        if (tid < NTRANS) {     // one-time setup by sub 0
            sLo[p] = lo; sHi[p] = hi;
            for (int o = 0; o < myL; o++) sIvl[myBase + o] = (unsigned short)p;
            // initial-value fix corrections (folded future fixes)
            const float* c4f = (const float*)g_c4;
            float run = 0.0f;
            for (int i = 0; i < myM; i++) {
                run += c4f[4 * i + psel];
                vv[myBase + (myM - 1 - i)] = v0 + run;
            }
        }
    }
    __syncthreads();

    int k = myL - 1;    // rotating slot offset of state o=0 (at block start)
    const int foldIdx = myM * 48 + psel;
    const float* c4f = (const float*)g_c4;

    // ================= 250 blocks x 24 frames =================
    for (int t0 = 0; t0 < NFRAMES; t0 += BFR) {
        // ---- gather phase: snapshot candidates for this thread's 8 frames ----
        if (act) {
            #pragma unroll
            for (int e = 0; e < SUBQ; e++) {
                int q  = qBase + e;
                int kg = k - q; if (kg < 0) kg += myL;
                float val = vv[srcBase + kg];
                sC[q * 256 + p] = val;
                g_cand[(t0 + q) * NTRANS + p] = val;
            }
        }
        if (tid >= NACT && tid < NACT + BFR + 8) {
            int u = tid - NACT;
            int fr = t0 + u; if (fr > NFRAMES - 1) fr = NFRAMES - 1;
            float4 c = g_c4[fr];
            sCC[2 * u]     = c.x;
            sCC[2 * u + 1] = c.y;
        }
        // fold-sum table: entry (m, q, ps) = sum_{i=1..m} c_ps(t0+q+i), guarded
        if (tid < 384) {
            int m  = tid / 48;
            int r  = tid - m * 48;
            int q  = r >> 1;
            int ps = r & 1;
            float acc = 0.0f;
            #pragma unroll 1
            for (int i = 1; i <= m; i++) {
                int fr = t0 + q + i;
                if (fr <= NFRAMES - 1) acc += c4f[4 * fr + ps];
            }
            foldT[tid] = acc;
        }
        __syncthreads();

        // ---- compute phase: 8 independent frames per thread ----
        if (act) {
            const float* ccp = sCC + psel;
            #pragma unroll 1
            for (int e = 0; e < SUBQ; e++) {
                int q  = qBase + e;
                int kw = k - q; if (kw < 0) kw += myL;
                const ulonglong2* c16 = (const ulonglong2*)(sC + q * 256 + cOff);
                float m0 = -3.0e38f, m1 = -3.0e38f, m2 = -3.0e38f, m3 = -3.0e38f;
                #pragma unroll
                for (int g = 0; g < WREG / 4; g++) {
                    ulonglong2 A = c16[g];
                    unsigned long long s0, s1;
                    float x, y;
                    ADDX2(s0, A.x, rP[2 * g]);     UNPK(x, y, s0);
                    m0 = fmaxf(m0, x); m1 = fmaxf(m1, y);
                    ADDX2(s1, A.y, rP[2 * g + 1]); UNPK(x, y, s1);
                    m2 = fmaxf(m2, x); m3 = fmaxf(m3, y);
                }
                float val = fmaxf(fmaxf(m0, m1), fmaxf(m2, m3));
                val += ccp[2 * q];
                val += foldT[foldIdx + 2 * q];
                vv[myBase + kw] = val;
            }
            k -= BFR; if (k < 0) k += myL;
        }
        __syncthreads();
    }

    // ================= argmax over final v (first-index tie-break) ============
    float bv = -3.0e38f;
    int   bi = 0x7FFFFFFF;
    if (tid < NTRANS) {
        int r = NFRAMES % myL;
        for (int o = 0; o < myL; o++) {
            int so = o - r; if (so < 0) so += myL;
            float x = vv[myBase + so];
            if (x > bv) { bv = x; bi = myBase + o; }
        }
    }
    rv[tid] = bv; ri[tid] = bi;
    __syncthreads();
    // 768 -> 256 fold (lexicographic merge is order-independent)
    if (tid < 256) {
        #pragma unroll
        for (int g = 1; g < 3; g++) {
            float xv = rv[tid + 256 * g]; int xi = ri[tid + 256 * g];
            if (xv > rv[tid] || (xv == rv[tid] && xi < ri[tid])) { rv[tid] = xv; ri[tid] = xi; }
        }
    }
    __syncthreads();
    for (int off = 128; off > 0; off >>= 1) {
        if (tid < off) {
            float xv = rv[tid + off]; int xi = ri[tid + off];
            if (xv > rv[tid] || (xv == rv[tid] && xi < ri[tid])) { rv[tid] = xv; ri[tid] = xi; }
        }
        __syncthreads();
    }

    // ================= backtrace (thread 0) =================
    if (tid == 0) {
        int s = ri[0];
        if (out_size > NFRAMES) out[NFRAMES] = rv[0] + *sSum;
        out[NFRAMES - 1] = (float)s;
        int t = NFRAMES - 1;
        while (t >= 1) {
            int iv = sIvl[s];
            int o  = s - sBase[iv];
            int steps = (o < t) ? o : t;
            for (int j = 1; j <= steps; j++) out[t - j] = (float)(s - j);
            t -= steps; s -= steps;
            if (t >= 1) {
                int b = iv / NTEMPI, i = iv - b * NTEMPI;
                const float* row  = lt2 + b * NTEMPI * LT_STRIDE + i * LT_STRIDE;
                const float* cand = g_cand + t * NTRANS + b * NTEMPI;
                int lo = sLo[iv], hi = sHi[iv];
                float best = -3.0e38f; int arg = lo;
                for (int j = lo; j <= hi; j++) {
                    float sc = cand[j] + row[j];
                    if (sc > best) { best = sc; arg = j; }
                }
                int pp = sPrev[b * NTEMPI + arg];
                out[t - 1] = (float)pp;
                s = pp; t--;
            }
        }
    }
}

extern "C" void kernel_launch(void* const* d_in, const int* in_sizes, int n_in,
                              void* d_out, int out_size) {
    const float* acts         = (const float*)d_in[0];
    const float* log_trans    = (const float*)d_in[1];
    const int*   prev_last    = (const int*)d_in[2];
    const int*   first_states = (const int*)d_in[3];
    const int*   pointer      = (const int*)d_in[4];
    int S = in_sizes[4];

    cudaFuncSetAttribute(viterbi_kernel, cudaFuncAttributeMaxDynamicSharedMemorySize, SMEM_BYTES);

    dens_kernel<<<(NFRAMES + 255) / 256, 256>>>(acts);
    viterbi_kernel<<<1, NT, SMEM_BYTES>>>(log_trans, prev_last, first_states, pointer,
                                          (float*)d_out, S, out_size);
}